// round 17
// baseline (speedup 1.0000x reference)
#include <cuda_runtime.h>
#include <math.h>

#define TPB 128
#define NPART 2048

__device__ float g_partials[NPART];
__device__ unsigned int g_count;

// One Sutherland-Hodgman clip pass -- FULLY BRANCH-FREE.
// Polygon lives in a thread-private smem column of float2 ([slot][tid],
// stride TPB -> conflict-free 64-bit accesses). Slot 9 is a per-thread
// trash slot: every push is an unconditional STS whose 32-bit offset is
// selected between the write cursor and trash, so no BSSY/BSYNC divergence.
// Wraparound handled by an appended copy of vertex 0 at slot np.
// In-place safe: all INCAP+1 slots are read before any write.
// Reads of slots >= np are predicate-discarded; garbage there is harmless.
// Reference semantics: keep = (val <= 0), crossing = strict sign change,
// frozen = empty result -> keep pre-clip polygon, stop clipping.
// Intersection uses the parametric form I = p + (v_p/(v_p-v_q))*(q-p).
template <int INCAP>
__device__ __forceinline__ void clip_edge_smem(float a, float b, float c,
                                               float2* __restrict__ sp,
                                               int t, int& np, bool& frozen) {
    bool doPass = !frozen && (np > 2);

    float2 r[INCAP + 1];
    float v[INCAP + 1];
#pragma unroll
    for (int j = 0; j <= INCAP; j++) {
        r[j] = sp[j * TPB + t];
        v[j] = a * r[j].x + b * r[j].y + c;
    }

    const int TRASH = 9 * TPB + t;   // per-thread trash slot offset
    int wo = t;                      // write cursor offset (32-bit)
    int nn = 0;
#pragma unroll
    for (int j = 0; j < INCAP; j++) {
        bool act  = doPass && (j < np);
        bool keep = act && (v[j] <= 0.0f);
        bool crs  = act && (v[j] * v[j + 1] < 0.0f);

        sp[keep ? wo : TRASH] = r[j];
        wo += keep ? TPB : 0;
        nn += keep ? 1 : 0;

        float w = __fdividef(v[j], v[j] - v[j + 1]);
        float2 ip;
        ip.x = fmaf(w, r[j + 1].x - r[j].x, r[j].x);
        ip.y = fmaf(w, r[j + 1].y - r[j].y, r[j].y);
        sp[crs ? wo : TRASH] = ip;
        wo += crs ? TPB : 0;
        nn += crs ? 1 : 0;
    }

    bool ok = doPass && (nn > 0);
    float2 f0 = sp[t];               // new slot 0 (if any push happened)
    sp[ok ? wo : TRASH] = f0;        // wo == nn*TPB + t
    np = ok ? nn : np;               // geometric bound: nn <= INCAP+1 <= 8
    frozen = frozen || (doPass && nn == 0);
}

__global__ void __launch_bounds__(TPB, 8)
giou_kernel(const float* __restrict__ pred,
            const float* __restrict__ tgt,
            float* __restrict__ out, int n) {
    __shared__ float2 s_xy[10 * TPB];  // clip polygon (+append, +trash slot)
    __shared__ float2 c_xy[8 * TPB];   // 8 corners (0-3 pred, 4-7 tgt)

    int t = threadIdx.x;
    int i = blockIdx.x * TPB + t;
    float giou = 0.0f;

    if (i < n) {
        const float2* pb = (const float2*)(pred + 6 * i);
        const float2* tb = (const float2*)(tgt + 6 * i);
        float2 p0 = __ldg(pb), p1 = __ldg(pb + 1), p2 = __ldg(pb + 2);
        float2 t0 = __ldg(tb), t1 = __ldg(tb + 1), t2 = __ldg(tb + 2);
        float area_sum = p1.x * p1.y + t1.x * t1.y;  // pa + ta

        // ---- corners into smem (float2); pred corners seed polygon + append ----
        {
            float rinv = rsqrtf(fmaf(p2.x, p2.x, p2.y * p2.y));
            float cth = p2.y * rinv, sth = p2.x * rinv;
            float hw = 0.5f * p1.x, hl = 0.5f * p1.y;
            float2 c0 = make_float2(p0.x - hw * cth - hl * sth, p0.y - hw * sth + hl * cth);
            float2 c1 = make_float2(p0.x - hw * cth + hl * sth, p0.y - hw * sth - hl * cth);
            float2 c2 = make_float2(p0.x + hw * cth + hl * sth, p0.y + hw * sth - hl * cth);
            float2 c3 = make_float2(p0.x + hw * cth - hl * sth, p0.y + hw * sth + hl * cth);
            c_xy[0 * TPB + t] = c0;  s_xy[0 * TPB + t] = c0;
            c_xy[1 * TPB + t] = c1;  s_xy[1 * TPB + t] = c1;
            c_xy[2 * TPB + t] = c2;  s_xy[2 * TPB + t] = c2;
            c_xy[3 * TPB + t] = c3;  s_xy[3 * TPB + t] = c3;
            s_xy[4 * TPB + t] = c0;  // append: wraparound copy of vertex 0
        }
        {
            float rinv = rsqrtf(fmaf(t2.x, t2.x, t2.y * t2.y));
            float cth = t2.y * rinv, sth = t2.x * rinv;
            float hw = 0.5f * t1.x, hl = 0.5f * t1.y;
            c_xy[4 * TPB + t] = make_float2(t0.x - hw * cth - hl * sth, t0.y - hw * sth + hl * cth);
            c_xy[5 * TPB + t] = make_float2(t0.x - hw * cth + hl * sth, t0.y - hw * sth - hl * cth);
            c_xy[6 * TPB + t] = make_float2(t0.x + hw * cth + hl * sth, t0.y + hw * sth - hl * cth);
            c_xy[7 * TPB + t] = make_float2(t0.x + hw * cth - hl * sth, t0.y + hw * sth + hl * cth);
        }

        // ---- clip by the 4 target half-planes (planes built JIT from smem) ----
        int np = 4;
        bool frozen = false;
#pragma unroll
        for (int e = 0; e < 4; e++) {
            const int e1 = (e + 1) & 3;
            float2 P = c_xy[(4 + e) * TPB + t];
            float2 Q = c_xy[(4 + e1) * TPB + t];
            float a = Q.y - P.y;
            float b = P.x - Q.x;
            float c = Q.x * P.y - Q.y * P.x;
            if (e == 0)      clip_edge_smem<4>(a, b, c, s_xy, t, np, frozen);
            else if (e == 1) clip_edge_smem<5>(a, b, c, s_xy, t, np, frozen);
            else if (e == 2) clip_edge_smem<6>(a, b, c, s_xy, t, np, frozen);
            else             clip_edge_smem<7>(a, b, c, s_xy, t, np, frozen);
        }

        // ---- shoelace over final polygon (append makes next = j+1) ----
        float s2 = 0.0f;
        {
            float2 q[9];
#pragma unroll
            for (int k = 0; k < 9; k++) q[k] = s_xy[k * TPB + t];
#pragma unroll
            for (int j = 0; j < 8; j++) {
                bool act = (j < np);
                float tm = q[j].x * q[j + 1].y - q[j].y * q[j + 1].x;
                s2 += act ? tm : 0.0f;
            }
        }
        float inter = (np > 2) ? 0.5f * fabsf(s2) : 0.0f;

        float uni = area_sum - inter;
        float iou = inter * __fdividef(1.0f, uni + 1e-16f);
        out[i] = iou;

        // ---- convex hull area, translated frame (P0 at origin) ----
        // Translation invariance: hull area and all edge-validity crosses
        // are invariant. With P0 = (0,0), every pairwise cross c_0j = 0, so
        // pairs involving point 0 contribute exactly 0 to the shoelace sum
        // and can be SKIPPED (21 pairs instead of 28). Edge test uses the
        // identity cross(Pj-Pi, Pk-Pi) = c_ij + c_jk - c_ik; the k=0 test
        // degenerates to c_ij itself.
        float2 Q0 = c_xy[0 * TPB + t];
        float2 P[8];
        P[0] = make_float2(0.0f, 0.0f);
#pragma unroll
        for (int k = 1; k < 8; k++) {
            float2 pk = c_xy[k * TPB + t];
            P[k] = make_float2(pk.x - Q0.x, pk.y - Q0.y);
        }
        float cc[64];
#pragma unroll
        for (int a = 1; a < 8; a++)
#pragma unroll
            for (int b2 = a + 1; b2 < 8; b2++)
                cc[a * 8 + b2] = P[a].x * P[b2].y - P[a].y * P[b2].x;

        float hs = 0.0f;
#pragma unroll
        for (int ii = 1; ii < 7; ii++) {
#pragma unroll
            for (int jj = ii + 1; jj < 8; jj++) {
                float cij = cc[ii * 8 + jj];
                float T[6];
                int c6 = 0;
                T[c6++] = cij;  // test at k = 0
#pragma unroll
                for (int k = 1; k < 8; k++) {
                    if (k == ii || k == jj) continue;  // cross == 0 there
                    float cjk = (jj < k) ? cc[jj * 8 + k] : -cc[k * 8 + jj];
                    float cik = (ii < k) ? cc[ii * 8 + k] : -cc[k * 8 + ii];
                    T[c6++] = cij + cjk - cik;
                }
                float mn = fminf(fminf(fminf(T[0], T[1]), fminf(T[2], T[3])),
                                 fminf(T[4], T[5]));
                float mx = fmaxf(fmaxf(fmaxf(T[0], T[1]), fmaxf(T[2], T[3])),
                                 fmaxf(T[4], T[5]));
                bool okL = (mn >= -1e-6f);  // ii -> jj valid hull edge
                bool okR = (mx <= 1e-6f);   // jj -> ii valid hull edge
                hs += okL ? cij : 0.0f;
                hs += okR ? -cij : 0.0f;
            }
        }
        float hull = 0.5f * fabsf(hs);

        giou = 1.0f - (iou - (hull - uni) * __fdividef(1.0f, hull + 1e-16f));
    }

    // ---- deterministic in-kernel reduction ----
#pragma unroll
    for (int off = 16; off > 0; off >>= 1)
        giou += __shfl_down_sync(0xffffffffu, giou, off);

    __shared__ float wsum[TPB / 32];
    __shared__ bool isLast;
    if ((t & 31) == 0) wsum[t >> 5] = giou;
    __syncthreads();

    if (t == 0) {
        float bs = 0.0f;
#pragma unroll
        for (int w = 0; w < TPB / 32; w++) bs += wsum[w];
        g_partials[blockIdx.x] = bs;
        __threadfence();
        unsigned c = atomicAdd(&g_count, 1u);
        isLast = (c == gridDim.x - 1);
    }
    __syncthreads();

    if (isLast) {
        __threadfence();
        float v = 0.0f;
        for (int j = t; j < (int)gridDim.x; j += TPB)
            v += ((volatile float*)g_partials)[j];
#pragma unroll
        for (int off = 16; off > 0; off >>= 1)
            v += __shfl_down_sync(0xffffffffu, v, off);
        if ((t & 31) == 0) wsum[t >> 5] = v;
        __syncthreads();
        if (t == 0) {
            float tot = 0.0f;
#pragma unroll
            for (int w = 0; w < TPB / 32; w++) tot += wsum[w];
            out[n] = tot;
            g_count = 0;  // reset for next graph replay
        }
    }
}

extern "C" void kernel_launch(void* const* d_in, const int* in_sizes, int n_in,
                              void* d_out, int out_size) {
    const float* pred = (const float*)d_in[0];
    const float* tgt  = (const float*)d_in[1];
    float* out = (float*)d_out;
    int n = in_sizes[0] / 6;
    int nblocks = (n + TPB - 1) / TPB;
    giou_kernel<<<nblocks, TPB>>>(pred, tgt, out, n);
}